// round 13
// baseline (speedup 1.0000x reference)
#include <cuda_runtime.h>
#include <cstdint>

#define FULLMASK 0xffffffffu

static constexpr int T_STEPS = 512;
static constexpr int INDIM   = 3;
static constexpr int H       = 32;
static constexpr int CHUNK   = 32;   // timesteps staged per smem refill
static constexpr int WARPS_PER_BLOCK = 4;

__device__ __forceinline__ unsigned long long pack2(float lo, float hi) {
    unsigned long long r;
    asm("mov.b64 %0, {%1, %2};" : "=l"(r) : "f"(lo), "f"(hi));
    return r;
}
__device__ __forceinline__ void unpack2(unsigned long long v, float &lo, float &hi) {
    asm("mov.b64 {%0, %1}, %2;" : "=f"(lo), "=f"(hi) : "l"(v));
}
// Packed dual-FMA: the full-rate fp32 path on sm_103a (3-reg FFMA is half-rate).
__device__ __forceinline__ unsigned long long fma2(unsigned long long a,
                                                   unsigned long long b,
                                                   unsigned long long c) {
    unsigned long long d;
    asm("fma.rn.f32x2 %0, %1, %2, %3;" : "=l"(d) : "l"(a), "l"(b), "l"(c));
    return d;
}
__device__ __forceinline__ unsigned long long add2(unsigned long long a,
                                                   unsigned long long b) {
    unsigned long long d;
    asm("add.rn.f32x2 %0, %1, %2;" : "=l"(d) : "l"(a), "l"(b));
    return d;
}

// Accurate-enough fast activations (~1e-6 rel err; __expf is ~2 ulp).
__device__ __forceinline__ float fast_sigmoid(float x) {
    float e = __expf(-x);
    return __fdividef(1.0f, 1.0f + e);
}
__device__ __forceinline__ float fast_tanh(float x) {
    // tanh(x) = 1 - 2/(e^{2x}+1); correct limits at +/-inf via IEEE inf/0.
    float e = __expf(2.0f * x);
    return 1.0f - __fdividef(2.0f, e + 1.0f);
}

__global__ __launch_bounds__(WARPS_PER_BLOCK * 32)
void lstm_fused_kernel(const float* __restrict__ x,
                       const float* __restrict__ W_ih,
                       const float* __restrict__ W_hh,
                       const float* __restrict__ b_ih,
                       const float* __restrict__ b_hh,
                       const float* __restrict__ W_fc,
                       const float* __restrict__ b_fc,
                       float* __restrict__ out)
{
    __shared__ float xs[WARPS_PER_BLOCK][CHUNK * INDIM];

    const int wib  = threadIdx.x >> 5;
    const int lane = threadIdx.x & 31;
    const int b    = blockIdx.x * WARPS_PER_BLOCK + wib;   // batch row

    // ---- Load weights into registers, packed as (i,f) and (g,o) gate pairs.
    // gates[r] = sum_k h[k] * W_hh[r, k]; rows: i=j, f=32+j, g=64+j, o=96+j (PyTorch order)
    unsigned long long Whh_if[H], Whh_go[H];
    #pragma unroll
    for (int k = 0; k < H; k++) {
        Whh_if[k] = pack2(W_hh[(0 * H + lane) * H + k], W_hh[(1 * H + lane) * H + k]);
        Whh_go[k] = pack2(W_hh[(2 * H + lane) * H + k], W_hh[(3 * H + lane) * H + k]);
    }
    unsigned long long Wih_if[INDIM], Wih_go[INDIM];
    #pragma unroll
    for (int i = 0; i < INDIM; i++) {
        Wih_if[i] = pack2(W_ih[(0 * H + lane) * INDIM + i], W_ih[(1 * H + lane) * INDIM + i]);
        Wih_go[i] = pack2(W_ih[(2 * H + lane) * INDIM + i], W_ih[(3 * H + lane) * INDIM + i]);
    }
    const unsigned long long bias_if =
        pack2(b_ih[0 * H + lane] + b_hh[0 * H + lane],
              b_ih[1 * H + lane] + b_hh[1 * H + lane]);
    const unsigned long long bias_go =
        pack2(b_ih[2 * H + lane] + b_hh[2 * H + lane],
              b_ih[3 * H + lane] + b_hh[3 * H + lane]);

    float h = 0.0f, c = 0.0f;
    const float* xb = x + (size_t)b * T_STEPS * INDIM;

    for (int t0 = 0; t0 < T_STEPS; t0 += CHUNK) {
        // Stage CHUNK timesteps of x (96 floats) into smem, coalesced.
        for (int i = lane; i < CHUNK * INDIM; i += 32)
            xs[wib][i] = xb[t0 * INDIM + i];
        __syncwarp();

        #pragma unroll 1   // keep body small: stay inside L0 I$
        for (int tt = 0; tt < CHUNK; tt++) {
            const float x0 = xs[wib][tt * 3 + 0];
            const float x1 = xs[wib][tt * 3 + 1];
            const float x2 = xs[wib][tt * 3 + 2];
            const unsigned long long xp0 = pack2(x0, x0);
            const unsigned long long xp1 = pack2(x1, x1);
            const unsigned long long xp2 = pack2(x2, x2);

            unsigned long long aif = fma2(xp0, Wih_if[0], bias_if);
            unsigned long long ago = fma2(xp0, Wih_go[0], bias_go);
            aif = fma2(xp1, Wih_if[1], aif);  ago = fma2(xp1, Wih_go[1], ago);
            aif = fma2(xp2, Wih_if[2], aif);  ago = fma2(xp2, Wih_go[2], ago);
            unsigned long long aif2 = 0ull, ago2 = 0ull;   // bits(0,0) == (0.f,0.f)

            // Recurrent matvec: 64 FFMA2 across 4 independent chains.
            #pragma unroll
            for (int k = 0; k < H; k += 2) {
                const float hk0 = __shfl_sync(FULLMASK, h, k);
                const float hk1 = __shfl_sync(FULLMASK, h, k + 1);
                const unsigned long long hp0 = pack2(hk0, hk0);
                const unsigned long long hp1 = pack2(hk1, hk1);
                aif  = fma2(hp0, Whh_if[k],     aif);
                ago  = fma2(hp0, Whh_go[k],     ago);
                aif2 = fma2(hp1, Whh_if[k + 1], aif2);
                ago2 = fma2(hp1, Whh_go[k + 1], ago2);
            }
            aif = add2(aif, aif2);
            ago = add2(ago, ago2);

            float gi, gf, gg, go;
            unpack2(aif, gi, gf);
            unpack2(ago, gg, go);

            const float iv = fast_sigmoid(gi);
            const float fv = fast_sigmoid(gf);
            const float gv = fast_tanh(gg);
            const float ov = fast_sigmoid(go);

            c = fv * c + iv * gv;
            h = ov * fast_tanh(c);
        }
        __syncwarp();
    }

    // ---- Final FC: out[b, o] = sum_j h[j] * W_fc[o, j] + b_fc[o], warp reduce.
    float p0 = h * W_fc[0 * H + lane];
    float p1 = h * W_fc[1 * H + lane];
    #pragma unroll
    for (int off = 16; off > 0; off >>= 1) {
        p0 += __shfl_xor_sync(FULLMASK, p0, off);
        p1 += __shfl_xor_sync(FULLMASK, p1, off);
    }
    if (lane == 0) {
        out[2 * b + 0] = p0 + b_fc[0];
        out[2 * b + 1] = p1 + b_fc[1];
    }
}

extern "C" void kernel_launch(void* const* d_in, const int* in_sizes, int n_in,
                              void* d_out, int out_size) {
    const float* x    = (const float*)d_in[0];
    const float* W_ih = (const float*)d_in[1];
    const float* W_hh = (const float*)d_in[2];
    const float* b_ih = (const float*)d_in[3];
    const float* b_hh = (const float*)d_in[4];
    const float* W_fc = (const float*)d_in[5];
    const float* b_fc = (const float*)d_in[6];
    float* out = (float*)d_out;

    const int B = in_sizes[0] / (T_STEPS * INDIM);   // 8192
    const int blocks = B / WARPS_PER_BLOCK;          // one warp per batch row

    lstm_fused_kernel<<<blocks, WARPS_PER_BLOCK * 32>>>(
        x, W_ih, W_hh, b_ih, b_hh, W_fc, b_fc, out);
}

// round 14
// speedup vs baseline: 1.0004x; 1.0004x over previous
#include <cuda_runtime.h>
#include <cstdint>

#define FULLMASK 0xffffffffu

static constexpr int T_STEPS = 512;
static constexpr int INDIM   = 3;
static constexpr int H       = 32;
static constexpr int CHUNK   = 32;   // timesteps staged per smem refill
static constexpr int WARPS_PER_BLOCK = 4;

__device__ __forceinline__ unsigned long long pack2(float lo, float hi) {
    unsigned long long r;
    asm("mov.b64 %0, {%1, %2};" : "=l"(r) : "f"(lo), "f"(hi));
    return r;
}
__device__ __forceinline__ void unpack2(unsigned long long v, float &lo, float &hi) {
    asm("mov.b64 {%0, %1}, %2;" : "=f"(lo), "=f"(hi) : "l"(v));
}
// Packed dual-FMA: the full-rate fp32 path on sm_103a (3-reg FFMA is half-rate).
__device__ __forceinline__ unsigned long long fma2(unsigned long long a,
                                                   unsigned long long b,
                                                   unsigned long long c) {
    unsigned long long d;
    asm("fma.rn.f32x2 %0, %1, %2, %3;" : "=l"(d) : "l"(a), "l"(b), "l"(c));
    return d;
}
__device__ __forceinline__ unsigned long long add2(unsigned long long a,
                                                   unsigned long long b) {
    unsigned long long d;
    asm("add.rn.f32x2 %0, %1, %2;" : "=l"(d) : "l"(a), "l"(b));
    return d;
}

// Accurate-enough fast activations (~1e-6 rel err; __expf is ~2 ulp).
__device__ __forceinline__ float fast_sigmoid(float x) {
    float e = __expf(-x);
    return __fdividef(1.0f, 1.0f + e);
}
__device__ __forceinline__ float fast_tanh(float x) {
    // tanh(x) = 1 - 2/(e^{2x}+1); correct limits at +/-inf via IEEE inf/0.
    float e = __expf(2.0f * x);
    return 1.0f - __fdividef(2.0f, e + 1.0f);
}

__global__ __launch_bounds__(WARPS_PER_BLOCK * 32)
void lstm_fused_kernel(const float* __restrict__ x,
                       const float* __restrict__ W_ih,
                       const float* __restrict__ W_hh,
                       const float* __restrict__ b_ih,
                       const float* __restrict__ b_hh,
                       const float* __restrict__ W_fc,
                       const float* __restrict__ b_fc,
                       float* __restrict__ out)
{
    __shared__ float xs[WARPS_PER_BLOCK][CHUNK * INDIM];

    const int wib  = threadIdx.x >> 5;
    const int lane = threadIdx.x & 31;
    const int b    = blockIdx.x * WARPS_PER_BLOCK + wib;   // batch row

    // ---- Load weights into registers, packed as (i,f) and (g,o) gate pairs.
    // gates[r] = sum_k h[k] * W_hh[r, k]; rows: i=j, f=32+j, g=64+j, o=96+j (PyTorch order)
    unsigned long long Whh_if[H], Whh_go[H];
    #pragma unroll
    for (int k = 0; k < H; k++) {
        Whh_if[k] = pack2(W_hh[(0 * H + lane) * H + k], W_hh[(1 * H + lane) * H + k]);
        Whh_go[k] = pack2(W_hh[(2 * H + lane) * H + k], W_hh[(3 * H + lane) * H + k]);
    }
    unsigned long long Wih_if[INDIM], Wih_go[INDIM];
    #pragma unroll
    for (int i = 0; i < INDIM; i++) {
        Wih_if[i] = pack2(W_ih[(0 * H + lane) * INDIM + i], W_ih[(1 * H + lane) * INDIM + i]);
        Wih_go[i] = pack2(W_ih[(2 * H + lane) * INDIM + i], W_ih[(3 * H + lane) * INDIM + i]);
    }
    const unsigned long long bias_if =
        pack2(b_ih[0 * H + lane] + b_hh[0 * H + lane],
              b_ih[1 * H + lane] + b_hh[1 * H + lane]);
    const unsigned long long bias_go =
        pack2(b_ih[2 * H + lane] + b_hh[2 * H + lane],
              b_ih[3 * H + lane] + b_hh[3 * H + lane]);

    float h = 0.0f, c = 0.0f;
    const float* xb = x + (size_t)b * T_STEPS * INDIM;

    for (int t0 = 0; t0 < T_STEPS; t0 += CHUNK) {
        // Stage CHUNK timesteps of x (96 floats) into smem, coalesced.
        for (int i = lane; i < CHUNK * INDIM; i += 32)
            xs[wib][i] = xb[t0 * INDIM + i];
        __syncwarp();

        #pragma unroll 1   // keep body small: stay inside L0 I$
        for (int tt = 0; tt < CHUNK; tt++) {
            const float x0 = xs[wib][tt * 3 + 0];
            const float x1 = xs[wib][tt * 3 + 1];
            const float x2 = xs[wib][tt * 3 + 2];
            const unsigned long long xp0 = pack2(x0, x0);
            const unsigned long long xp1 = pack2(x1, x1);
            const unsigned long long xp2 = pack2(x2, x2);

            unsigned long long aif = fma2(xp0, Wih_if[0], bias_if);
            unsigned long long ago = fma2(xp0, Wih_go[0], bias_go);
            aif = fma2(xp1, Wih_if[1], aif);  ago = fma2(xp1, Wih_go[1], ago);
            aif = fma2(xp2, Wih_if[2], aif);  ago = fma2(xp2, Wih_go[2], ago);
            unsigned long long aif2 = 0ull, ago2 = 0ull;   // bits(0,0) == (0.f,0.f)

            // Recurrent matvec: 64 FFMA2 across 4 independent chains.
            #pragma unroll
            for (int k = 0; k < H; k += 2) {
                const float hk0 = __shfl_sync(FULLMASK, h, k);
                const float hk1 = __shfl_sync(FULLMASK, h, k + 1);
                const unsigned long long hp0 = pack2(hk0, hk0);
                const unsigned long long hp1 = pack2(hk1, hk1);
                aif  = fma2(hp0, Whh_if[k],     aif);
                ago  = fma2(hp0, Whh_go[k],     ago);
                aif2 = fma2(hp1, Whh_if[k + 1], aif2);
                ago2 = fma2(hp1, Whh_go[k + 1], ago2);
            }
            aif = add2(aif, aif2);
            ago = add2(ago, ago2);

            float gi, gf, gg, go;
            unpack2(aif, gi, gf);
            unpack2(ago, gg, go);

            const float iv = fast_sigmoid(gi);
            const float fv = fast_sigmoid(gf);
            const float gv = fast_tanh(gg);
            const float ov = fast_sigmoid(go);

            c = fv * c + iv * gv;
            h = ov * fast_tanh(c);
        }
        __syncwarp();
    }

    // ---- Final FC: out[b, o] = sum_j h[j] * W_fc[o, j] + b_fc[o], warp reduce.
    float p0 = h * W_fc[0 * H + lane];
    float p1 = h * W_fc[1 * H + lane];
    #pragma unroll
    for (int off = 16; off > 0; off >>= 1) {
        p0 += __shfl_xor_sync(FULLMASK, p0, off);
        p1 += __shfl_xor_sync(FULLMASK, p1, off);
    }
    if (lane == 0) {
        out[2 * b + 0] = p0 + b_fc[0];
        out[2 * b + 1] = p1 + b_fc[1];
    }
}

extern "C" void kernel_launch(void* const* d_in, const int* in_sizes, int n_in,
                              void* d_out, int out_size) {
    const float* x    = (const float*)d_in[0];
    const float* W_ih = (const float*)d_in[1];
    const float* W_hh = (const float*)d_in[2];
    const float* b_ih = (const float*)d_in[3];
    const float* b_hh = (const float*)d_in[4];
    const float* W_fc = (const float*)d_in[5];
    const float* b_fc = (const float*)d_in[6];
    float* out = (float*)d_out;

    const int B = in_sizes[0] / (T_STEPS * INDIM);   // 8192
    const int blocks = B / WARPS_PER_BLOCK;          // one warp per batch row

    lstm_fused_kernel<<<blocks, WARPS_PER_BLOCK * 32>>>(
        x, W_ih, W_hh, b_ih, b_hh, W_fc, b_fc, out);
}

// round 15
// speedup vs baseline: 1.0013x; 1.0008x over previous
#include <cuda_runtime.h>
#include <cstdint>

#define FULLMASK 0xffffffffu

static constexpr int T_STEPS = 512;
static constexpr int INDIM   = 3;
static constexpr int H       = 32;
static constexpr int CHUNK   = 32;   // timesteps staged per smem refill
static constexpr int WARPS_PER_BLOCK = 4;

__device__ __forceinline__ unsigned long long pack2(float lo, float hi) {
    unsigned long long r;
    asm("mov.b64 %0, {%1, %2};" : "=l"(r) : "f"(lo), "f"(hi));
    return r;
}
__device__ __forceinline__ void unpack2(unsigned long long v, float &lo, float &hi) {
    asm("mov.b64 {%0, %1}, %2;" : "=f"(lo), "=f"(hi) : "l"(v));
}
// Packed dual-FMA: the full-rate fp32 path on sm_103a (3-reg FFMA is half-rate).
__device__ __forceinline__ unsigned long long fma2(unsigned long long a,
                                                   unsigned long long b,
                                                   unsigned long long c) {
    unsigned long long d;
    asm("fma.rn.f32x2 %0, %1, %2, %3;" : "=l"(d) : "l"(a), "l"(b), "l"(c));
    return d;
}
__device__ __forceinline__ unsigned long long add2(unsigned long long a,
                                                   unsigned long long b) {
    unsigned long long d;
    asm("add.rn.f32x2 %0, %1, %2;" : "=l"(d) : "l"(a), "l"(b));
    return d;
}

// Accurate-enough fast activations (~1e-6 rel err; __expf is ~2 ulp).
__device__ __forceinline__ float fast_sigmoid(float x) {
    float e = __expf(-x);
    return __fdividef(1.0f, 1.0f + e);
}
__device__ __forceinline__ float fast_tanh(float x) {
    // tanh(x) = 1 - 2/(e^{2x}+1); correct limits at +/-inf via IEEE inf/0.
    float e = __expf(2.0f * x);
    return 1.0f - __fdividef(2.0f, e + 1.0f);
}

__global__ __launch_bounds__(WARPS_PER_BLOCK * 32)
void lstm_fused_kernel(const float* __restrict__ x,
                       const float* __restrict__ W_ih,
                       const float* __restrict__ W_hh,
                       const float* __restrict__ b_ih,
                       const float* __restrict__ b_hh,
                       const float* __restrict__ W_fc,
                       const float* __restrict__ b_fc,
                       float* __restrict__ out)
{
    __shared__ float xs[WARPS_PER_BLOCK][CHUNK * INDIM];

    const int wib  = threadIdx.x >> 5;
    const int lane = threadIdx.x & 31;
    const int b    = blockIdx.x * WARPS_PER_BLOCK + wib;   // batch row

    // ---- Load weights into registers, packed as (i,f) and (g,o) gate pairs.
    // gates[r] = sum_k h[k] * W_hh[r, k]; rows: i=j, f=32+j, g=64+j, o=96+j (PyTorch order)
    unsigned long long Whh_if[H], Whh_go[H];
    #pragma unroll
    for (int k = 0; k < H; k++) {
        Whh_if[k] = pack2(W_hh[(0 * H + lane) * H + k], W_hh[(1 * H + lane) * H + k]);
        Whh_go[k] = pack2(W_hh[(2 * H + lane) * H + k], W_hh[(3 * H + lane) * H + k]);
    }
    unsigned long long Wih_if[INDIM], Wih_go[INDIM];
    #pragma unroll
    for (int i = 0; i < INDIM; i++) {
        Wih_if[i] = pack2(W_ih[(0 * H + lane) * INDIM + i], W_ih[(1 * H + lane) * INDIM + i]);
        Wih_go[i] = pack2(W_ih[(2 * H + lane) * INDIM + i], W_ih[(3 * H + lane) * INDIM + i]);
    }
    const unsigned long long bias_if =
        pack2(b_ih[0 * H + lane] + b_hh[0 * H + lane],
              b_ih[1 * H + lane] + b_hh[1 * H + lane]);
    const unsigned long long bias_go =
        pack2(b_ih[2 * H + lane] + b_hh[2 * H + lane],
              b_ih[3 * H + lane] + b_hh[3 * H + lane]);

    float h = 0.0f, c = 0.0f;
    const float* xb = x + (size_t)b * T_STEPS * INDIM;

    for (int t0 = 0; t0 < T_STEPS; t0 += CHUNK) {
        // Stage CHUNK timesteps of x (96 floats) into smem, coalesced.
        for (int i = lane; i < CHUNK * INDIM; i += 32)
            xs[wib][i] = xb[t0 * INDIM + i];
        __syncwarp();

        #pragma unroll 1   // keep body small: stay inside L0 I$
        for (int tt = 0; tt < CHUNK; tt++) {
            const float x0 = xs[wib][tt * 3 + 0];
            const float x1 = xs[wib][tt * 3 + 1];
            const float x2 = xs[wib][tt * 3 + 2];
            const unsigned long long xp0 = pack2(x0, x0);
            const unsigned long long xp1 = pack2(x1, x1);
            const unsigned long long xp2 = pack2(x2, x2);

            unsigned long long aif = fma2(xp0, Wih_if[0], bias_if);
            unsigned long long ago = fma2(xp0, Wih_go[0], bias_go);
            aif = fma2(xp1, Wih_if[1], aif);  ago = fma2(xp1, Wih_go[1], ago);
            aif = fma2(xp2, Wih_if[2], aif);  ago = fma2(xp2, Wih_go[2], ago);
            unsigned long long aif2 = 0ull, ago2 = 0ull;   // bits(0,0) == (0.f,0.f)

            // Recurrent matvec: 64 FFMA2 across 4 independent chains.
            #pragma unroll
            for (int k = 0; k < H; k += 2) {
                const float hk0 = __shfl_sync(FULLMASK, h, k);
                const float hk1 = __shfl_sync(FULLMASK, h, k + 1);
                const unsigned long long hp0 = pack2(hk0, hk0);
                const unsigned long long hp1 = pack2(hk1, hk1);
                aif  = fma2(hp0, Whh_if[k],     aif);
                ago  = fma2(hp0, Whh_go[k],     ago);
                aif2 = fma2(hp1, Whh_if[k + 1], aif2);
                ago2 = fma2(hp1, Whh_go[k + 1], ago2);
            }
            aif = add2(aif, aif2);
            ago = add2(ago, ago2);

            float gi, gf, gg, go;
            unpack2(aif, gi, gf);
            unpack2(ago, gg, go);

            const float iv = fast_sigmoid(gi);
            const float fv = fast_sigmoid(gf);
            const float gv = fast_tanh(gg);
            const float ov = fast_sigmoid(go);

            c = fv * c + iv * gv;
            h = ov * fast_tanh(c);
        }
        __syncwarp();
    }

    // ---- Final FC: out[b, o] = sum_j h[j] * W_fc[o, j] + b_fc[o], warp reduce.
    float p0 = h * W_fc[0 * H + lane];
    float p1 = h * W_fc[1 * H + lane];
    #pragma unroll
    for (int off = 16; off > 0; off >>= 1) {
        p0 += __shfl_xor_sync(FULLMASK, p0, off);
        p1 += __shfl_xor_sync(FULLMASK, p1, off);
    }
    if (lane == 0) {
        out[2 * b + 0] = p0 + b_fc[0];
        out[2 * b + 1] = p1 + b_fc[1];
    }
}

extern "C" void kernel_launch(void* const* d_in, const int* in_sizes, int n_in,
                              void* d_out, int out_size) {
    const float* x    = (const float*)d_in[0];
    const float* W_ih = (const float*)d_in[1];
    const float* W_hh = (const float*)d_in[2];
    const float* b_ih = (const float*)d_in[3];
    const float* b_hh = (const float*)d_in[4];
    const float* W_fc = (const float*)d_in[5];
    const float* b_fc = (const float*)d_in[6];
    float* out = (float*)d_out;

    const int B = in_sizes[0] / (T_STEPS * INDIM);   // 8192
    const int blocks = B / WARPS_PER_BLOCK;          // one warp per batch row

    lstm_fused_kernel<<<blocks, WARPS_PER_BLOCK * 32>>>(
        x, W_ih, W_hh, b_ih, b_hh, W_fc, b_fc, out);
}

// round 16
// speedup vs baseline: 1.0021x; 1.0008x over previous
#include <cuda_runtime.h>
#include <cstdint>

#define FULLMASK 0xffffffffu

static constexpr int T_STEPS = 512;
static constexpr int INDIM   = 3;
static constexpr int H       = 32;
static constexpr int CHUNK   = 32;   // timesteps staged per smem refill
static constexpr int WARPS_PER_BLOCK = 4;

__device__ __forceinline__ unsigned long long pack2(float lo, float hi) {
    unsigned long long r;
    asm("mov.b64 %0, {%1, %2};" : "=l"(r) : "f"(lo), "f"(hi));
    return r;
}
__device__ __forceinline__ void unpack2(unsigned long long v, float &lo, float &hi) {
    asm("mov.b64 {%0, %1}, %2;" : "=f"(lo), "=f"(hi) : "l"(v));
}
// Packed dual-FMA: the full-rate fp32 path on sm_103a (3-reg FFMA is half-rate).
__device__ __forceinline__ unsigned long long fma2(unsigned long long a,
                                                   unsigned long long b,
                                                   unsigned long long c) {
    unsigned long long d;
    asm("fma.rn.f32x2 %0, %1, %2, %3;" : "=l"(d) : "l"(a), "l"(b), "l"(c));
    return d;
}
__device__ __forceinline__ unsigned long long add2(unsigned long long a,
                                                   unsigned long long b) {
    unsigned long long d;
    asm("add.rn.f32x2 %0, %1, %2;" : "=l"(d) : "l"(a), "l"(b));
    return d;
}

// Accurate-enough fast activations (~1e-6 rel err; __expf is ~2 ulp).
__device__ __forceinline__ float fast_sigmoid(float x) {
    float e = __expf(-x);
    return __fdividef(1.0f, 1.0f + e);
}
__device__ __forceinline__ float fast_tanh(float x) {
    // tanh(x) = 1 - 2/(e^{2x}+1); correct limits at +/-inf via IEEE inf/0.
    float e = __expf(2.0f * x);
    return 1.0f - __fdividef(2.0f, e + 1.0f);
}

__global__ __launch_bounds__(WARPS_PER_BLOCK * 32)
void lstm_fused_kernel(const float* __restrict__ x,
                       const float* __restrict__ W_ih,
                       const float* __restrict__ W_hh,
                       const float* __restrict__ b_ih,
                       const float* __restrict__ b_hh,
                       const float* __restrict__ W_fc,
                       const float* __restrict__ b_fc,
                       float* __restrict__ out)
{
    __shared__ float xs[WARPS_PER_BLOCK][CHUNK * INDIM];

    const int wib  = threadIdx.x >> 5;
    const int lane = threadIdx.x & 31;
    const int b    = blockIdx.x * WARPS_PER_BLOCK + wib;   // batch row

    // ---- Load weights into registers, packed as (i,f) and (g,o) gate pairs.
    // gates[r] = sum_k h[k] * W_hh[r, k]; rows: i=j, f=32+j, g=64+j, o=96+j (PyTorch order)
    unsigned long long Whh_if[H], Whh_go[H];
    #pragma unroll
    for (int k = 0; k < H; k++) {
        Whh_if[k] = pack2(W_hh[(0 * H + lane) * H + k], W_hh[(1 * H + lane) * H + k]);
        Whh_go[k] = pack2(W_hh[(2 * H + lane) * H + k], W_hh[(3 * H + lane) * H + k]);
    }
    unsigned long long Wih_if[INDIM], Wih_go[INDIM];
    #pragma unroll
    for (int i = 0; i < INDIM; i++) {
        Wih_if[i] = pack2(W_ih[(0 * H + lane) * INDIM + i], W_ih[(1 * H + lane) * INDIM + i]);
        Wih_go[i] = pack2(W_ih[(2 * H + lane) * INDIM + i], W_ih[(3 * H + lane) * INDIM + i]);
    }
    const unsigned long long bias_if =
        pack2(b_ih[0 * H + lane] + b_hh[0 * H + lane],
              b_ih[1 * H + lane] + b_hh[1 * H + lane]);
    const unsigned long long bias_go =
        pack2(b_ih[2 * H + lane] + b_hh[2 * H + lane],
              b_ih[3 * H + lane] + b_hh[3 * H + lane]);

    float h = 0.0f, c = 0.0f;
    const float* xb = x + (size_t)b * T_STEPS * INDIM;

    for (int t0 = 0; t0 < T_STEPS; t0 += CHUNK) {
        // Stage CHUNK timesteps of x (96 floats) into smem, coalesced.
        for (int i = lane; i < CHUNK * INDIM; i += 32)
            xs[wib][i] = xb[t0 * INDIM + i];
        __syncwarp();

        #pragma unroll 1   // keep body small: stay inside L0 I$
        for (int tt = 0; tt < CHUNK; tt++) {
            const float x0 = xs[wib][tt * 3 + 0];
            const float x1 = xs[wib][tt * 3 + 1];
            const float x2 = xs[wib][tt * 3 + 2];
            const unsigned long long xp0 = pack2(x0, x0);
            const unsigned long long xp1 = pack2(x1, x1);
            const unsigned long long xp2 = pack2(x2, x2);

            unsigned long long aif = fma2(xp0, Wih_if[0], bias_if);
            unsigned long long ago = fma2(xp0, Wih_go[0], bias_go);
            aif = fma2(xp1, Wih_if[1], aif);  ago = fma2(xp1, Wih_go[1], ago);
            aif = fma2(xp2, Wih_if[2], aif);  ago = fma2(xp2, Wih_go[2], ago);
            unsigned long long aif2 = 0ull, ago2 = 0ull;   // bits(0,0) == (0.f,0.f)

            // Recurrent matvec: 64 FFMA2 across 4 independent chains.
            #pragma unroll
            for (int k = 0; k < H; k += 2) {
                const float hk0 = __shfl_sync(FULLMASK, h, k);
                const float hk1 = __shfl_sync(FULLMASK, h, k + 1);
                const unsigned long long hp0 = pack2(hk0, hk0);
                const unsigned long long hp1 = pack2(hk1, hk1);
                aif  = fma2(hp0, Whh_if[k],     aif);
                ago  = fma2(hp0, Whh_go[k],     ago);
                aif2 = fma2(hp1, Whh_if[k + 1], aif2);
                ago2 = fma2(hp1, Whh_go[k + 1], ago2);
            }
            aif = add2(aif, aif2);
            ago = add2(ago, ago2);

            float gi, gf, gg, go;
            unpack2(aif, gi, gf);
            unpack2(ago, gg, go);

            const float iv = fast_sigmoid(gi);
            const float fv = fast_sigmoid(gf);
            const float gv = fast_tanh(gg);
            const float ov = fast_sigmoid(go);

            c = fv * c + iv * gv;
            h = ov * fast_tanh(c);
        }
        __syncwarp();
    }

    // ---- Final FC: out[b, o] = sum_j h[j] * W_fc[o, j] + b_fc[o], warp reduce.
    float p0 = h * W_fc[0 * H + lane];
    float p1 = h * W_fc[1 * H + lane];
    #pragma unroll
    for (int off = 16; off > 0; off >>= 1) {
        p0 += __shfl_xor_sync(FULLMASK, p0, off);
        p1 += __shfl_xor_sync(FULLMASK, p1, off);
    }
    if (lane == 0) {
        out[2 * b + 0] = p0 + b_fc[0];
        out[2 * b + 1] = p1 + b_fc[1];
    }
}

extern "C" void kernel_launch(void* const* d_in, const int* in_sizes, int n_in,
                              void* d_out, int out_size) {
    const float* x    = (const float*)d_in[0];
    const float* W_ih = (const float*)d_in[1];
    const float* W_hh = (const float*)d_in[2];
    const float* b_ih = (const float*)d_in[3];
    const float* b_hh = (const float*)d_in[4];
    const float* W_fc = (const float*)d_in[5];
    const float* b_fc = (const float*)d_in[6];
    float* out = (float*)d_out;

    const int B = in_sizes[0] / (T_STEPS * INDIM);   // 8192
    const int blocks = B / WARPS_PER_BLOCK;          // one warp per batch row

    lstm_fused_kernel<<<blocks, WARPS_PER_BLOCK * 32>>>(
        x, W_ih, W_hh, b_ih, b_hh, W_fc, b_fc, out);
}